// round 9
// baseline (speedup 1.0000x reference)
#include <cuda_runtime.h>
#include <cuda_bf16.h>
#include <cstdint>
#include <cstddef>

#define TSTEPS 1000
#define NBINS 10
#define SBIN 100

// ---------------- scratch (static device memory; no allocations) ----------------
// conv pre-activations (float), spike trains (uint8, values exactly 0/1)
__device__ float   g_c1[(size_t)TSTEPS*4*50*184];
__device__ uint8_t g_s1[(size_t)TSTEPS*4*50*184];
__device__ float   g_c2[(size_t)TSTEPS*8*25*92];
__device__ uint8_t g_s2[(size_t)TSTEPS*8*25*92];
__device__ float   g_c3[(size_t)TSTEPS*16*13*46];
__device__ uint8_t g_s3[(size_t)TSTEPS*16*13*46];
__device__ float   g_c4[(size_t)TSTEPS*32*7*23];
__device__ float g_sk1[80*50*184];
__device__ float g_sk2[160*25*92];
__device__ float g_sk3[320*13*46];
__device__ float g_sk4[640*7*23];
__device__ float g_d4[64*7*23];
__device__ float g_u4[64*13*46];
__device__ float g_d3[32*13*46];
__device__ float g_u3[32*25*92];
__device__ float g_d2[16*25*92];
__device__ float g_u2[16*50*184];
__device__ float g_d1[8*50*184];
__device__ float g_u1[8*100*368];

// ---------------- encoder conv: stride-2 3x3 SAME, batched over all t ----------------
// grid = (y-groups, t). Each thread computes a 4co x 4x tile for one output row.
// ST = source element type (float for layer 1 input, uint8_t for spike trains).
// W lo-pad is 0 for every layer; H lo-pad is PADH (0,0,1,1).
template<typename ST,int CIN,int COUT,int HI,int WI,int HO,int WO,int PADH>
__global__ void enc_conv_kernel(const ST* __restrict__ src,     // [T][CIN][HI][WI]
                                const float* __restrict__ w,    // [COUT][CIN][3][3]
                                const float* __restrict__ bias, // [COUT]
                                float* __restrict__ dst)        // [T][COUT][HO][WO]
{
    constexpr int GY  = 4;                       // output rows per block (9 input rows)
    constexpr int XT  = (WO + 3) / 4;            // x-tiles
    constexpr int COT = COUT / 4;                // co-tiles
    constexpr int SW0 = ((WI + 4) / 4) * 4;
    constexpr int SW1 = 8 * (XT - 1) + 12;
    constexpr int SW  = (SW0 > SW1) ? SW0 : SW1; // multiple of 4

    __shared__ alignas(16) float sm_in[CIN * 9 * SW];
    __shared__ alignas(16) float sm_w[CIN * 9 * COUT];
    __shared__ float sm_b[COUT];

    const int t     = blockIdx.y;
    const int ybase = blockIdx.x * GY;
    const int tid   = threadIdx.x;
    const int nthr  = blockDim.x;

    // transposed weights: sm_w[(ci*9 + kh*3 + kw)*COUT + co]
    for (int i = tid; i < COUT * CIN * 9; i += nthr) {
        int co   = i % COUT;
        int rest = i / COUT;               // ci*9 + kk
        int ci   = rest / 9;
        int kk   = rest % 9;
        sm_w[i] = w[(co * CIN + ci) * 9 + kk];
    }
    for (int i = tid; i < COUT; i += nthr) sm_b[i] = bias[i];

    const int rowbase = 2 * ybase - PADH;
    const ST* srct = src + (size_t)t * CIN * HI * WI;
    for (int i = tid; i < CIN * 9 * SW; i += nthr) {
        int col = i % SW;
        int r   = (i / SW) % 9;
        int ci  = i / (SW * 9);
        int row = rowbase + r;
        float v = 0.f;
        if (row >= 0 && row < HI && col < WI)
            v = (float)srct[((size_t)ci * HI + row) * WI + col];
        sm_in[i] = v;
    }
    __syncthreads();

    const int yloc = tid / (COT * XT);
    const int rem  = tid % (COT * XT);
    const int co0  = (rem / XT) * 4;
    const int x0   = (rem % XT) * 4;
    const int y    = ybase + yloc;
    if (yloc >= GY || y >= HO) return;

    float acc[4][4];
    #pragma unroll
    for (int i = 0; i < 4; i++)
        #pragma unroll
        for (int j = 0; j < 4; j++) acc[i][j] = 0.f;

    for (int ci = 0; ci < CIN; ci++) {
        #pragma unroll
        for (int kh = 0; kh < 3; kh++) {
            const float* rp = &sm_in[(ci * 9 + 2 * yloc + kh) * SW + 2 * x0];
            float4 v0 = *(const float4*)rp;
            float4 v1 = *(const float4*)(rp + 4);
            float4 v2 = *(const float4*)(rp + 8);
            float in_[12] = {v0.x,v0.y,v0.z,v0.w, v1.x,v1.y,v1.z,v1.w, v2.x,v2.y,v2.z,v2.w};
            #pragma unroll
            for (int kw = 0; kw < 3; kw++) {
                const float4 wv = *(const float4*)&sm_w[(ci*9 + kh*3 + kw)*COUT + co0];
                #pragma unroll
                for (int j = 0; j < 4; j++) {
                    float iv = in_[kw + 2*j];
                    acc[0][j] = fmaf(wv.x, iv, acc[0][j]);
                    acc[1][j] = fmaf(wv.y, iv, acc[1][j]);
                    acc[2][j] = fmaf(wv.z, iv, acc[2][j]);
                    acc[3][j] = fmaf(wv.w, iv, acc[3][j]);
                }
            }
        }
    }

    float* dp = dst + (size_t)t * COUT * HO * WO + (size_t)y * WO;
    #pragma unroll
    for (int i = 0; i < 4; i++) {
        int co = co0 + i;
        float bv = sm_b[co];
        float* o = dp + (size_t)co * HO * WO;
        if ((WO % 4 == 0) && (x0 + 4 <= WO)) {
            float4 ov = make_float4(acc[i][0]+bv, acc[i][1]+bv, acc[i][2]+bv, acc[i][3]+bv);
            *(float4*)(o + x0) = ov;
        } else {
            #pragma unroll
            for (int j = 0; j < 4; j++)
                if (x0 + j < WO) o[x0 + j] = acc[i][j] + bv;
        }
    }
}

// ---------------- membrane scan: one thread per neuron, sequential in t ----------------
// m = 0.9*m + c (NON-fused mul+add to match XLA); spk = (m > 1); m -= spk;
// per-bin mean/std written directly into the skip-connection channel layout.
// Spikes stored as uint8 (exactly 0/1); conversion is lossless.
// LDB = load batch width (MLP). MUST divide SBIN exactly (bug in R4-R8: LDB=8
// with SBIN=100 overran each bin by 4 steps and double-applied them).
template<int C,int HWN,bool WRITE_SPK,int LDB>
__global__ void scan_kernel(const float* __restrict__ cbuf,   // [T][C][HWN]
                            uint8_t* __restrict__ spk,        // [T][C][HWN] (or unused)
                            float* __restrict__ skip)         // [K*2*C][HWN]
{
    static_assert(SBIN % LDB == 0, "LDB must divide SBIN");
    constexpr int N = C * HWN;
    int idx = blockIdx.x * blockDim.x + threadIdx.x;
    if (idx >= N) return;
    const int c  = idx / HWN;
    const int sp = idx % HWN;
    float m = 0.f;
    const float* cp = cbuf + idx;

    for (int k = 0; k < NBINS; k++) {
        float sum = 0.f, sq = 0.f;
        for (int s = 0; s < SBIN; s += LDB) {
            const int t0 = k * SBIN + s;
            // batch LDB independent loads (addresses independent of m) -> MLP>=LDB
            float vv[LDB];
            #pragma unroll
            for (int q = 0; q < LDB; q++)
                vv[q] = cp[(size_t)(t0 + q) * N];
            #pragma unroll
            for (int q = 0; q < LDB; q++) {
                m = __fadd_rn(__fmul_rn(0.9f, m), vv[q]);
                float spike = (m > 1.0f) ? 1.0f : 0.0f;   // exact heaviside(m-1>0)
                m = __fadd_rn(m, -spike);                 // soft reset, THR=1
                if (WRITE_SPK) spk[(size_t)(t0 + q) * N + idx] = (uint8_t)spike;
                sum += m;
                sq  = fmaf(m, m, sq);
            }
        }
        float mu  = sum / 100.0f;
        float var = sq / 100.0f - mu * mu;
        float sd  = sqrtf(fmaxf(var, 1e-8f));
        skip[((size_t)(k*2+0)*C + c)*HWN + sp] = mu;
        skip[((size_t)(k*2+1)*C + c)*HWN + sp] = sd;
    }
}

// ---------------- decoder conv: stride-1 3x3 SAME + ReLU, on concat(up, skip) ----------------
// grid = (H, CG). Each block computes COUT/CG channels of one output row; ci chunked.
template<int CUP,int CSK,int COUT,int H,int W,int CG>
__global__ void dec_conv_kernel(const float* __restrict__ up,
                                const float* __restrict__ sk,
                                const float* __restrict__ w,     // [COUT][CIN][3][3]
                                const float* __restrict__ bias,
                                float* __restrict__ out)
{
    constexpr int CIN = CUP + CSK;
    constexpr int CC  = 16;                 // ci chunk
    constexpr int SMW = W + 4;
    constexpr int COB = COUT / CG;
    constexpr int OUTS = COB * W;
    constexpr int PERT = (OUTS + 255) / 256;

    __shared__ float smv[3 * CC * SMW];
    __shared__ float smw[COB * CC * 9];

    const int y    = blockIdx.x;
    const int cob0 = blockIdx.y * COB;
    const int tid  = threadIdx.x;

    float acc[PERT];
    #pragma unroll
    for (int i = 0; i < PERT; i++) acc[i] = 0.f;

    for (int cc = 0; cc < CIN; cc += CC) {
        __syncthreads();
        // input chunk tile: rows y-1..y+1, cols -1..W
        for (int li = tid; li < 3 * CC * SMW; li += 256) {
            int col = li % SMW;
            int ci  = (li / SMW) % CC;
            int r   = li / (SMW * CC);
            int row  = y + r - 1;
            int icol = col - 1;
            float v = 0.f;
            int cig = cc + ci;
            if (row >= 0 && row < H && icol >= 0 && icol < W) {
                if (CUP > 0 && cig < CUP)
                    v = up[((size_t)cig * H + row) * W + icol];
                else
                    v = sk[((size_t)(cig - CUP) * H + row) * W + icol];
            }
            smv[li] = v;
        }
        // weight chunk
        for (int li = tid; li < COB * CC * 9; li += 256) {
            int kk   = li % 9;
            int ci   = (li / 9) % CC;
            int co_l = li / (9 * CC);
            smw[li] = w[((size_t)(cob0 + co_l) * CIN + cc + ci) * 9 + kk];
        }
        __syncthreads();

        #pragma unroll
        for (int i = 0; i < PERT; i++) {
            int o = tid + i * 256;
            if (o < OUTS) {
                int co_l = o / W;
                int x    = o % W;
                float a = acc[i];
                for (int ci = 0; ci < CC; ci++) {
                    #pragma unroll
                    for (int kh = 0; kh < 3; kh++) {
                        #pragma unroll
                        for (int kw = 0; kw < 3; kw++) {
                            a = fmaf(smw[(co_l*CC + ci)*9 + kh*3 + kw],
                                     smv[(kh*CC + ci)*SMW + x + kw], a);
                        }
                    }
                }
                acc[i] = a;
            }
        }
    }

    #pragma unroll
    for (int i = 0; i < PERT; i++) {
        int o = tid + i * 256;
        if (o < OUTS) {
            int co = cob0 + o / W;
            int x  = o % W;
            float v = acc[i] + __ldg(bias + co);
            v = fmaxf(v, 0.f);
            out[((size_t)co * H + y) * W + x] = v;
        }
    }
}

// ---------------- bilinear upsample (jax 'bilinear': half-pixel; edge renorm == clamp) ----------------
template<int C,int HI,int WI,int HO,int WO>
__global__ void up_kernel(const float* __restrict__ in, float* __restrict__ out)
{
    int idx = blockIdx.x * blockDim.x + threadIdx.x;
    if (idx >= C * HO * WO) return;
    int c  = idx / (HO * WO);
    int oy = (idx / WO) % HO;
    int ox = idx % WO;
    float fy = (oy + 0.5f) * ((float)HI / (float)HO) - 0.5f;
    float fx = (ox + 0.5f) * ((float)WI / (float)WO) - 0.5f;
    int y0 = (int)floorf(fy);
    int x0 = (int)floorf(fx);
    float dy = fy - (float)y0;
    float dx = fx - (float)x0;
    int y0c = min(max(y0,     0), HI - 1);
    int y1c = min(max(y0 + 1, 0), HI - 1);
    int x0c = min(max(x0,     0), WI - 1);
    int x1c = min(max(x0 + 1, 0), WI - 1);
    const float* p = in + (size_t)c * HI * WI;
    float v00 = p[y0c * WI + x0c], v01 = p[y0c * WI + x1c];
    float v10 = p[y1c * WI + x0c], v11 = p[y1c * WI + x1c];
    float v0 = v00 + dx * (v01 - v00);
    float v1 = v10 + dx * (v11 - v10);
    out[idx] = v0 + dy * (v1 - v0);
}

// ---------------- final 1x1 conv (no relu) ----------------
__global__ void out_conv_kernel(const float* __restrict__ u,   // [8][100][368]
                                const float* __restrict__ wo,  // [1][8][1][1]
                                const float* __restrict__ bo,  // [1]
                                float* __restrict__ out)       // [1][1][100][368]
{
    int idx = blockIdx.x * blockDim.x + threadIdx.x;
    if (idx >= 100 * 368) return;
    float a = bo[0];
    #pragma unroll
    for (int c = 0; c < 8; c++)
        a = fmaf(wo[c], u[(size_t)c * 36800 + idx], a);
    out[idx] = a;
}

// ---------------- host ----------------
template<typename T>
static T* sym(const void* s) {
    void* p = nullptr;
    cudaGetSymbolAddress(&p, s);
    return (T*)p;
}

extern "C" void kernel_launch(void* const* d_in, const int* in_sizes, int n_in,
                              void* d_out, int out_size)
{
    const float* x   = (const float*)d_in[0];
    const float* w1  = (const float*)d_in[1];
    const float* b1  = (const float*)d_in[2];
    const float* w2  = (const float*)d_in[3];
    const float* b2  = (const float*)d_in[4];
    const float* w3  = (const float*)d_in[5];
    const float* b3  = (const float*)d_in[6];
    const float* w4  = (const float*)d_in[7];
    const float* b4  = (const float*)d_in[8];
    const float* dw4 = (const float*)d_in[9];
    const float* db4 = (const float*)d_in[10];
    const float* dw3 = (const float*)d_in[11];
    const float* db3 = (const float*)d_in[12];
    const float* dw2 = (const float*)d_in[13];
    const float* db2 = (const float*)d_in[14];
    const float* dw1 = (const float*)d_in[15];
    const float* db1 = (const float*)d_in[16];
    const float* wo  = (const float*)d_in[17];
    const float* bo  = (const float*)d_in[18];
    float* out = (float*)d_out;

    float*   c1  = sym<float>(g_c1);    uint8_t* s1 = sym<uint8_t>(g_s1);
    float*   c2  = sym<float>(g_c2);    uint8_t* s2 = sym<uint8_t>(g_s2);
    float*   c3  = sym<float>(g_c3);    uint8_t* s3 = sym<uint8_t>(g_s3);
    float*   c4  = sym<float>(g_c4);
    float* sk1 = sym<float>(g_sk1); float* sk2 = sym<float>(g_sk2);
    float* sk3 = sym<float>(g_sk3); float* sk4 = sym<float>(g_sk4);
    float* d4  = sym<float>(g_d4);  float* u4 = sym<float>(g_u4);
    float* d3  = sym<float>(g_d3);  float* u3 = sym<float>(g_u3);
    float* d2  = sym<float>(g_d2);  float* u2 = sym<float>(g_u2);
    float* d1  = sym<float>(g_d1);  float* u1 = sym<float>(g_u1);

    // ---- encoder: conv (batched over t) alternating with membrane scan ----
    enc_conv_kernel<float,  1, 4,100,368,50,184,0><<<dim3(13,TSTEPS),184>>>(x,  w1, b1, c1);
    scan_kernel<4, 9200, true ,10><<<(36800+255)/256,256>>>(c1, s1, sk1);
    enc_conv_kernel<uint8_t,4, 8, 50,184,25, 92,0><<<dim3( 7,TSTEPS),184>>>(s1, w2, b2, c2);
    scan_kernel<8, 2300, true ,10><<<(18400+255)/256,256>>>(c2, s2, sk2);
    enc_conv_kernel<uint8_t,8,16, 25, 92,13, 46,1><<<dim3( 4,TSTEPS),192>>>(s2, w3, b3, c3);
    scan_kernel<16, 598, true ,10><<<( 9568+255)/256,256>>>(c3, s3, sk3);
    enc_conv_kernel<uint8_t,16,32, 13, 46, 7, 23,1><<<dim3( 2,TSTEPS),192>>>(s3, w4, b4, c4);
    scan_kernel<32, 161, false,10><<<( 5152+255)/256,256>>>(c4, nullptr, sk4);

    // ---- decoder ----
    dec_conv_kernel< 0,640,64, 7, 23,8><<<dim3( 7,8),256>>>(nullptr, sk4, dw4, db4, d4);
    up_kernel<64, 7, 23,13, 46><<<(64*13*46 +255)/256,256>>>(d4, u4);
    dec_conv_kernel<64,320,32,13, 46,4><<<dim3(13,4),256>>>(u4, sk3, dw3, db3, d3);
    up_kernel<32,13, 46,25, 92><<<(32*25*92 +255)/256,256>>>(d3, u3);
    dec_conv_kernel<32,160,16,25, 92,2><<<dim3(25,2),256>>>(u3, sk2, dw2, db2, d2);
    up_kernel<16,25, 92,50,184><<<(16*50*184+255)/256,256>>>(d2, u2);
    dec_conv_kernel<16, 80, 8,50,184,2><<<dim3(50,2),256>>>(u2, sk1, dw1, db1, d1);
    up_kernel< 8,50,184,100,368><<<(8*100*368+255)/256,256>>>(d1, u1);
    out_conv_kernel<<<(36800+255)/256,256>>>(u1, wo, bo, out);
}

// round 13
// speedup vs baseline: 1.2164x; 1.2164x over previous
#include <cuda_runtime.h>
#include <cuda_bf16.h>
#include <cstdint>
#include <cstddef>

#define TSTEPS 1000
#define NBINS 10
#define SBIN 100

// ---------------- scratch (static device memory; no allocations) ----------------
__device__ float   g_c1[(size_t)TSTEPS*4*50*184];
__device__ uint8_t g_s1[(size_t)TSTEPS*4*50*184];
__device__ float   g_c2[(size_t)TSTEPS*8*25*92];
__device__ uint8_t g_s2[(size_t)TSTEPS*8*25*92];
__device__ float   g_c3[(size_t)TSTEPS*16*13*46];
__device__ uint8_t g_s3[(size_t)TSTEPS*16*13*46];
__device__ float   g_c4[(size_t)TSTEPS*32*7*23];
__device__ float g_sk1[80*50*184];
__device__ float g_sk2[160*25*92];
__device__ float g_sk3[320*13*46];
__device__ float g_sk4[640*7*23];
__device__ float g_d4[64*7*23];
__device__ float g_u4[64*13*46];
__device__ float g_d3[32*13*46];
__device__ float g_u3[32*25*92];
__device__ float g_d2[16*25*92];
__device__ float g_u2[16*50*184];
__device__ float g_d1[8*50*184];
__device__ float g_u1[8*100*368];

// ---------------- encoder conv: stride-2 3x3 SAME, batched over all t ----------------
template<typename ST,int CIN,int COUT,int HI,int WI,int HO,int WO,int PADH>
__global__ void enc_conv_kernel(const ST* __restrict__ src,     // [T][CIN][HI][WI]
                                const float* __restrict__ w,    // [COUT][CIN][3][3]
                                const float* __restrict__ bias, // [COUT]
                                float* __restrict__ dst)        // [T][COUT][HO][WO]
{
    constexpr int GY  = 4;
    constexpr int XT  = (WO + 3) / 4;
    constexpr int COT = COUT / 4;
    constexpr int SW0 = ((WI + 4) / 4) * 4;
    constexpr int SW1 = 8 * (XT - 1) + 12;
    constexpr int SW  = (SW0 > SW1) ? SW0 : SW1;

    __shared__ alignas(16) float sm_in[CIN * 9 * SW];
    __shared__ alignas(16) float sm_w[CIN * 9 * COUT];
    __shared__ float sm_b[COUT];

    const int t     = blockIdx.y;
    const int ybase = blockIdx.x * GY;
    const int tid   = threadIdx.x;
    const int nthr  = blockDim.x;

    for (int i = tid; i < COUT * CIN * 9; i += nthr) {
        int co   = i % COUT;
        int rest = i / COUT;
        int ci   = rest / 9;
        int kk   = rest % 9;
        sm_w[i] = w[(co * CIN + ci) * 9 + kk];
    }
    for (int i = tid; i < COUT; i += nthr) sm_b[i] = bias[i];

    const int rowbase = 2 * ybase - PADH;
    const ST* srct = src + (size_t)t * CIN * HI * WI;
    for (int i = tid; i < CIN * 9 * SW; i += nthr) {
        int col = i % SW;
        int r   = (i / SW) % 9;
        int ci  = i / (SW * 9);
        int row = rowbase + r;
        float v = 0.f;
        if (row >= 0 && row < HI && col < WI)
            v = (float)srct[((size_t)ci * HI + row) * WI + col];
        sm_in[i] = v;
    }
    __syncthreads();

    const int yloc = tid / (COT * XT);
    const int rem  = tid % (COT * XT);
    const int co0  = (rem / XT) * 4;
    const int x0   = (rem % XT) * 4;
    const int y    = ybase + yloc;
    if (yloc >= GY || y >= HO) return;

    float acc[4][4];
    #pragma unroll
    for (int i = 0; i < 4; i++)
        #pragma unroll
        for (int j = 0; j < 4; j++) acc[i][j] = 0.f;

    for (int ci = 0; ci < CIN; ci++) {
        #pragma unroll
        for (int kh = 0; kh < 3; kh++) {
            const float* rp = &sm_in[(ci * 9 + 2 * yloc + kh) * SW + 2 * x0];
            float4 v0 = *(const float4*)rp;
            float4 v1 = *(const float4*)(rp + 4);
            float4 v2 = *(const float4*)(rp + 8);
            float in_[12] = {v0.x,v0.y,v0.z,v0.w, v1.x,v1.y,v1.z,v1.w, v2.x,v2.y,v2.z,v2.w};
            #pragma unroll
            for (int kw = 0; kw < 3; kw++) {
                const float4 wv = *(const float4*)&sm_w[(ci*9 + kh*3 + kw)*COUT + co0];
                #pragma unroll
                for (int j = 0; j < 4; j++) {
                    float iv = in_[kw + 2*j];
                    acc[0][j] = fmaf(wv.x, iv, acc[0][j]);
                    acc[1][j] = fmaf(wv.y, iv, acc[1][j]);
                    acc[2][j] = fmaf(wv.z, iv, acc[2][j]);
                    acc[3][j] = fmaf(wv.w, iv, acc[3][j]);
                }
            }
        }
    }

    float* dp = dst + (size_t)t * COUT * HO * WO + (size_t)y * WO;
    #pragma unroll
    for (int i = 0; i < 4; i++) {
        int co = co0 + i;
        float bv = sm_b[co];
        float* o = dp + (size_t)co * HO * WO;
        if ((WO % 4 == 0) && (x0 + 4 <= WO)) {
            float4 ov = make_float4(acc[i][0]+bv, acc[i][1]+bv, acc[i][2]+bv, acc[i][3]+bv);
            *(float4*)(o + x0) = ov;
        } else {
            #pragma unroll
            for (int j = 0; j < 4; j++)
                if (x0 + j < WO) o[x0 + j] = acc[i][j] + bv;
        }
    }
}

// ---------------- membrane scan: depth-1 prefetch, LDB=20 ----------------
// Compute per batch (20 steps x ~29 cyc dependent chain) >= 577-cyc DRAM latency,
// so the prefetched loads for batch b+1 are fully hidden under batch b's compute.
// Arithmetic identical to the validated R9 kernel (non-fused mul+add, exact heaviside).
template<int C,int HWN,bool WRITE_SPK,int LDB>
__global__ void scan_kernel(const float* __restrict__ cbuf,   // [T][C][HWN]
                            uint8_t* __restrict__ spk,        // [T][C][HWN] (or unused)
                            float* __restrict__ skip)         // [K*2*C][HWN]
{
    static_assert(SBIN % LDB == 0, "LDB must divide SBIN");
    constexpr int N      = C * HWN;
    constexpr int NBATCH = TSTEPS / LDB;
    constexpr int BPB    = SBIN / LDB;      // batches per bin
    int idx = blockIdx.x * blockDim.x + threadIdx.x;
    if (idx >= N) return;
    const int c  = idx / HWN;
    const int sp = idx % HWN;
    const float* cp = cbuf + idx;

    float cur[LDB], nxt[LDB];
    #pragma unroll
    for (int q = 0; q < LDB; q++)
        cur[q] = cp[(size_t)q * N];

    float m = 0.f, sum = 0.f, sq = 0.f;
    int k = 0;
    for (int b = 0; b < NBATCH; b++) {
        // prefetch next batch (independent addresses -> overlaps with chain below)
        if (b + 1 < NBATCH) {
            #pragma unroll
            for (int q = 0; q < LDB; q++)
                nxt[q] = cp[(size_t)((b + 1) * LDB + q) * N];
        }
        const int t0 = b * LDB;
        #pragma unroll
        for (int q = 0; q < LDB; q++) {
            m = __fadd_rn(__fmul_rn(0.9f, m), cur[q]);
            float spike = (m > 1.0f) ? 1.0f : 0.0f;   // exact heaviside(m-1>0)
            m = __fadd_rn(m, -spike);                 // soft reset, THR=1
            if (WRITE_SPK) spk[(size_t)(t0 + q) * N + idx] = (uint8_t)spike;
            sum += m;
            sq  = fmaf(m, m, sq);
        }
        if ((b + 1) % BPB == 0) {
            float mu  = sum / 100.0f;
            float var = sq / 100.0f - mu * mu;
            float sd  = sqrtf(fmaxf(var, 1e-8f));
            skip[((size_t)(k*2+0)*C + c)*HWN + sp] = mu;
            skip[((size_t)(k*2+1)*C + c)*HWN + sp] = sd;
            k++; sum = 0.f; sq = 0.f;
        }
        #pragma unroll
        for (int q = 0; q < LDB; q++) cur[q] = nxt[q];
    }
}

// ---------------- decoder conv: stride-1 3x3 SAME + ReLU, on concat(up, skip) ----------------
template<int CUP,int CSK,int COUT,int H,int W,int CG>
__global__ void dec_conv_kernel(const float* __restrict__ up,
                                const float* __restrict__ sk,
                                const float* __restrict__ w,
                                const float* __restrict__ bias,
                                float* __restrict__ out)
{
    constexpr int CIN = CUP + CSK;
    constexpr int CC  = 16;
    constexpr int SMW = W + 4;
    constexpr int COB = COUT / CG;
    constexpr int OUTS = COB * W;
    constexpr int PERT = (OUTS + 255) / 256;

    __shared__ float smv[3 * CC * SMW];
    __shared__ float smw[COB * CC * 9];

    const int y    = blockIdx.x;
    const int cob0 = blockIdx.y * COB;
    const int tid  = threadIdx.x;

    float acc[PERT];
    #pragma unroll
    for (int i = 0; i < PERT; i++) acc[i] = 0.f;

    for (int cc = 0; cc < CIN; cc += CC) {
        __syncthreads();
        for (int li = tid; li < 3 * CC * SMW; li += 256) {
            int col = li % SMW;
            int ci  = (li / SMW) % CC;
            int r   = li / (SMW * CC);
            int row  = y + r - 1;
            int icol = col - 1;
            float v = 0.f;
            int cig = cc + ci;
            if (row >= 0 && row < H && icol >= 0 && icol < W) {
                if (CUP > 0 && cig < CUP)
                    v = up[((size_t)cig * H + row) * W + icol];
                else
                    v = sk[((size_t)(cig - CUP) * H + row) * W + icol];
            }
            smv[li] = v;
        }
        for (int li = tid; li < COB * CC * 9; li += 256) {
            int kk   = li % 9;
            int ci   = (li / 9) % CC;
            int co_l = li / (9 * CC);
            smw[li] = w[((size_t)(cob0 + co_l) * CIN + cc + ci) * 9 + kk];
        }
        __syncthreads();

        #pragma unroll
        for (int i = 0; i < PERT; i++) {
            int o = tid + i * 256;
            if (o < OUTS) {
                int co_l = o / W;
                int x    = o % W;
                float a = acc[i];
                for (int ci = 0; ci < CC; ci++) {
                    #pragma unroll
                    for (int kh = 0; kh < 3; kh++) {
                        #pragma unroll
                        for (int kw = 0; kw < 3; kw++) {
                            a = fmaf(smw[(co_l*CC + ci)*9 + kh*3 + kw],
                                     smv[(kh*CC + ci)*SMW + x + kw], a);
                        }
                    }
                }
                acc[i] = a;
            }
        }
    }

    #pragma unroll
    for (int i = 0; i < PERT; i++) {
        int o = tid + i * 256;
        if (o < OUTS) {
            int co = cob0 + o / W;
            int x  = o % W;
            float v = acc[i] + __ldg(bias + co);
            v = fmaxf(v, 0.f);
            out[((size_t)co * H + y) * W + x] = v;
        }
    }
}

// ---------------- bilinear upsample (jax half-pixel + clamp) ----------------
template<int C,int HI,int WI,int HO,int WO>
__global__ void up_kernel(const float* __restrict__ in, float* __restrict__ out)
{
    int idx = blockIdx.x * blockDim.x + threadIdx.x;
    if (idx >= C * HO * WO) return;
    int c  = idx / (HO * WO);
    int oy = (idx / WO) % HO;
    int ox = idx % WO;
    float fy = (oy + 0.5f) * ((float)HI / (float)HO) - 0.5f;
    float fx = (ox + 0.5f) * ((float)WI / (float)WO) - 0.5f;
    int y0 = (int)floorf(fy);
    int x0 = (int)floorf(fx);
    float dy = fy - (float)y0;
    float dx = fx - (float)x0;
    int y0c = min(max(y0,     0), HI - 1);
    int y1c = min(max(y0 + 1, 0), HI - 1);
    int x0c = min(max(x0,     0), WI - 1);
    int x1c = min(max(x0 + 1, 0), WI - 1);
    const float* p = in + (size_t)c * HI * WI;
    float v00 = p[y0c * WI + x0c], v01 = p[y0c * WI + x1c];
    float v10 = p[y1c * WI + x0c], v11 = p[y1c * WI + x1c];
    float v0 = v00 + dx * (v01 - v00);
    float v1 = v10 + dx * (v11 - v10);
    out[idx] = v0 + dy * (v1 - v0);
}

// ---------------- final 1x1 conv (no relu) ----------------
__global__ void out_conv_kernel(const float* __restrict__ u,
                                const float* __restrict__ wo,
                                const float* __restrict__ bo,
                                float* __restrict__ out)
{
    int idx = blockIdx.x * blockDim.x + threadIdx.x;
    if (idx >= 100 * 368) return;
    float a = bo[0];
    #pragma unroll
    for (int c = 0; c < 8; c++)
        a = fmaf(wo[c], u[(size_t)c * 36800 + idx], a);
    out[idx] = a;
}

// ---------------- host ----------------
template<typename T>
static T* sym(const void* s) {
    void* p = nullptr;
    cudaGetSymbolAddress(&p, s);
    return (T*)p;
}

extern "C" void kernel_launch(void* const* d_in, const int* in_sizes, int n_in,
                              void* d_out, int out_size)
{
    const float* x   = (const float*)d_in[0];
    const float* w1  = (const float*)d_in[1];
    const float* b1  = (const float*)d_in[2];
    const float* w2  = (const float*)d_in[3];
    const float* b2  = (const float*)d_in[4];
    const float* w3  = (const float*)d_in[5];
    const float* b3  = (const float*)d_in[6];
    const float* w4  = (const float*)d_in[7];
    const float* b4  = (const float*)d_in[8];
    const float* dw4 = (const float*)d_in[9];
    const float* db4 = (const float*)d_in[10];
    const float* dw3 = (const float*)d_in[11];
    const float* db3 = (const float*)d_in[12];
    const float* dw2 = (const float*)d_in[13];
    const float* db2 = (const float*)d_in[14];
    const float* dw1 = (const float*)d_in[15];
    const float* db1 = (const float*)d_in[16];
    const float* wo  = (const float*)d_in[17];
    const float* bo  = (const float*)d_in[18];
    float* out = (float*)d_out;

    float*   c1  = sym<float>(g_c1);    uint8_t* s1 = sym<uint8_t>(g_s1);
    float*   c2  = sym<float>(g_c2);    uint8_t* s2 = sym<uint8_t>(g_s2);
    float*   c3  = sym<float>(g_c3);    uint8_t* s3 = sym<uint8_t>(g_s3);
    float*   c4  = sym<float>(g_c4);
    float* sk1 = sym<float>(g_sk1); float* sk2 = sym<float>(g_sk2);
    float* sk3 = sym<float>(g_sk3); float* sk4 = sym<float>(g_sk4);
    float* d4  = sym<float>(g_d4);  float* u4 = sym<float>(g_u4);
    float* d3  = sym<float>(g_d3);  float* u3 = sym<float>(g_u3);
    float* d2  = sym<float>(g_d2);  float* u2 = sym<float>(g_u2);
    float* d1  = sym<float>(g_d1);  float* u1 = sym<float>(g_u1);

    // ---- encoder: conv (batched over t) alternating with membrane scan ----
    // scan block sizes spread blocks across the 148 SMs:
    // L1: 144x256, L2: 144x128, L3: 150x64, L4: 81x64
    enc_conv_kernel<float,  1, 4,100,368,50,184,0><<<dim3(13,TSTEPS),184>>>(x,  w1, b1, c1);
    scan_kernel<4, 9200, true ,20><<<(36800+255)/256,256>>>(c1, s1, sk1);
    enc_conv_kernel<uint8_t,4, 8, 50,184,25, 92,0><<<dim3( 7,TSTEPS),184>>>(s1, w2, b2, c2);
    scan_kernel<8, 2300, true ,20><<<(18400+127)/128,128>>>(c2, s2, sk2);
    enc_conv_kernel<uint8_t,8,16, 25, 92,13, 46,1><<<dim3( 4,TSTEPS),192>>>(s2, w3, b3, c3);
    scan_kernel<16, 598, true ,20><<<( 9568+63)/64,64>>>(c3, s3, sk3);
    enc_conv_kernel<uint8_t,16,32, 13, 46, 7, 23,1><<<dim3( 2,TSTEPS),192>>>(s3, w4, b4, c4);
    scan_kernel<32, 161, false,20><<<( 5152+63)/64,64>>>(c4, nullptr, sk4);

    // ---- decoder ----
    dec_conv_kernel< 0,640,64, 7, 23,8><<<dim3( 7,8),256>>>(nullptr, sk4, dw4, db4, d4);
    up_kernel<64, 7, 23,13, 46><<<(64*13*46 +255)/256,256>>>(d4, u4);
    dec_conv_kernel<64,320,32,13, 46,4><<<dim3(13,4),256>>>(u4, sk3, dw3, db3, d3);
    up_kernel<32,13, 46,25, 92><<<(32*25*92 +255)/256,256>>>(d3, u3);
    dec_conv_kernel<32,160,16,25, 92,2><<<dim3(25,2),256>>>(u3, sk2, dw2, db2, d2);
    up_kernel<16,25, 92,50,184><<<(16*50*184+255)/256,256>>>(d2, u2);
    dec_conv_kernel<16, 80, 8,50,184,2><<<dim3(50,2),256>>>(u2, sk1, dw1, db1, d1);
    up_kernel< 8,50,184,100,368><<<(8*100*368+255)/256,256>>>(d1, u1);
    out_conv_kernel<<<(36800+255)/256,256>>>(u1, wo, bo, out);
}